// round 4
// baseline (speedup 1.0000x reference)
#include <cuda_runtime.h>
#include <cuda_bf16.h>
#include <cstdint>

#define HW   256
#define HW2  65536
#define NT   1024                      // threads per CTA (one CTA per batch)

// dynamic SMEM layout: [0, 131072) uint16 winner table (as 32768 uint32 words)
//                      [131072, 139264) seg>0.5 bitmask (2048 uint32 words)
#define SMEM_BYTES (131072 + 8192)

// 16-bit atomic max emulated with 32-bit CAS (cells packed 2/word).
__device__ __forceinline__ void smax16(uint32_t* table, int cell, uint32_t val) {
    uint32_t* w = &table[cell >> 1];
    int sh = (cell & 1) << 4;
    uint32_t old = *w;
    while (((old >> sh) & 0xFFFFu) < val) {
        uint32_t assumed = old;
        uint32_t neu = (old & ~(0xFFFFu << sh)) | (val << sh);
        old = atomicCAS(w, assumed, neu);
        if (old == assumed) break;
    }
}

__global__ void __launch_bounds__(NT, 1)
dsf_fused_kernel(const float* __restrict__ grid,
                 const float* __restrict__ seg,
                 const float* __restrict__ conf,
                 const float* __restrict__ depth,
                 float* __restrict__ out, int bs) {
    extern __shared__ uint32_t smem[];
    uint32_t* table = smem;            // 65536 uint16 cells, init 0 (== empty == winner 0)
    uint32_t* bits  = smem + 32768;    // 2048 words
    __shared__ int s_cnt[NT / 32], s_mm[NT / 32];
    __shared__ int s_emp, s_mmax;

    int b    = blockIdx.x;
    int tid  = threadIdx.x;
    int warp = tid >> 5, lane = tid & 31;
    const float* segb = seg + (size_t)b * HW2;

    // ---- Phase A: zero table (SMEM) + bitmask + count + max masked index ----
    uint4* t4 = reinterpret_cast<uint4*>(table);
    #pragma unroll
    for (int i = 0; i < 8; i++)
        t4[i * NT + tid] = make_uint4(0u, 0u, 0u, 0u);

    int cnt = 0, mm = -1;
    int wbase = warp << 11;            // 2048 px per warp
    #pragma unroll 4
    for (int j = 0; j < 64; j++) {
        int idx = wbase + (j << 5) + lane;
        bool m = __ldcs(segb + idx) > 0.5f;
        unsigned word = __ballot_sync(0xffffffffu, m);
        if (lane == 0) bits[idx >> 5] = word;
        cnt += m;
        if (!m) mm = idx;              // ascending -> final = max masked idx
    }
    #pragma unroll
    for (int o = 16; o; o >>= 1) {
        cnt += __shfl_down_sync(0xffffffffu, cnt, o);
        mm  = max(mm, __shfl_down_sync(0xffffffffu, mm, o));
    }
    if (lane == 0) { s_cnt[warp] = cnt; s_mm[warp] = mm; }
    __syncthreads();
    if (tid == 0) {
        int c = 0, m2 = -1;
        #pragma unroll
        for (int i = 0; i < NT / 32; i++) { c += s_cnt[i]; m2 = max(m2, s_mm[i]); }
        s_emp  = (c == 0);
        s_mmax = m2;
    }
    __syncthreads();
    const bool emp = (s_emp != 0);

    // ---- Phase B: scatter valid pixels into SMEM table (16-bit max-CAS) ----
    // Masked pixels all map to cell (128,128); deduped to ONE op via s_mmax.
    const float* gxb = grid + (size_t)b * 2 * HW2;
    const float* gyb = gxb + HW2;
    #pragma unroll 2
    for (int g = 0; g < HW2 / (NT * 4); g++) {      // 16 groups of 4 px
        int p = (g * NT + tid) << 2;
        unsigned word = bits[p >> 5];
        float4 gx4 = __ldcs(reinterpret_cast<const float4*>(gxb + p));
        float4 gy4 = __ldcs(reinterpret_cast<const float4*>(gyb + p));
        float gx[4] = {gx4.x, gx4.y, gx4.z, gx4.w};
        float gy[4] = {gy4.x, gy4.y, gy4.z, gy4.w};
        #pragma unroll
        for (int k = 0; k < 4; k++) {
            if (emp || ((word >> ((p + k) & 31)) & 1u)) {
                int ix = (int)((gx[k] + 1.0f) * 0.5f * (float)HW);
                int iy = (int)((gy[k] + 1.0f) * 0.5f * (float)HW);
                ix = min(max(ix, 0), HW - 1);
                iy = min(max(iy, 0), HW - 1);
                smax16(table, iy * HW + ix, (uint32_t)(p + k));
            }
        }
    }
    if (tid == 0 && !emp && s_mmax >= 0)
        smax16(table, 128 * HW + 128, (uint32_t)s_mmax);
    __syncthreads();

    // ---- Phase C: decode winners, nearest-sample, write 5 output planes ----
    // ix = w_src & ~1, iy = h_src & ~1 (round-half-even collapse); empty==0 -> (0,0).
    const float* db = depth + (size_t)b * HW2;
    const float* cb = conf  + (size_t)b * HW2;
    #pragma unroll 2
    for (int g = 0; g < HW2 / (NT * 4); g++) {
        int p = (g * NT + tid) << 2;
        uint2 tw = *reinterpret_cast<uint2*>(reinterpret_cast<char*>(table) + p * 2);
        uint32_t s[4] = {tw.x & 0xFFFFu, tw.x >> 16, tw.y & 0xFFFFu, tw.y >> 16};

        float4 ox, oy, od, oc, om;
        float *oxp = &ox.x, *oyp = &oy.x, *odp = &od.x, *ocp = &oc.x, *omp = &om.x;
        #pragma unroll
        for (int k = 0; k < 4; k++) {
            int ix = (int)(s[k] & (HW - 1)) & ~1;
            int iy = (int)(s[k] >> 8) & ~1;
            int cell = iy * HW + ix;
            float m = (emp || ((bits[cell >> 5] >> (cell & 31)) & 1u)) ? 1.0f : 0.0f;
            float d = __ldg(db + cell);
            float c = __ldg(cb + cell);
            oxp[k] = ((float)ix * (1.0f / 280.0f)) * m;
            oyp[k] = ((float)iy * (1.0f / 280.0f)) * m;
            odp[k] = d * m;
            ocp[k] = c;
            omp[k] = m;
        }
        size_t o0 = (size_t)b * 3 * HW2 + p;
        __stcs(reinterpret_cast<float4*>(out + o0),           ox);
        __stcs(reinterpret_cast<float4*>(out + o0 + HW2),     oy);
        __stcs(reinterpret_cast<float4*>(out + o0 + 2 * HW2), od);
        __stcs(reinterpret_cast<float4*>(out + (size_t)bs * 3 * HW2 + (size_t)b * HW2 + p), oc);
        __stcs(reinterpret_cast<float4*>(out + (size_t)bs * 4 * HW2 + (size_t)b * HW2 + p), om);
    }
}

// ---------------------------------------------------------------------------
extern "C" void kernel_launch(void* const* d_in, const int* in_sizes, int n_in,
                              void* d_out, int out_size) {
    const float* grid  = (const float*)d_in[0];
    const float* seg   = (const float*)d_in[1];
    const float* conf  = (const float*)d_in[2];
    const float* depth = (const float*)d_in[3];
    float* out = (float*)d_out;

    int bs = in_sizes[1] / HW2;   // 128

    cudaFuncSetAttribute(dsf_fused_kernel,
                         cudaFuncAttributeMaxDynamicSharedMemorySize, SMEM_BYTES);
    dsf_fused_kernel<<<bs, NT, SMEM_BYTES>>>(grid, seg, conf, depth, out, bs);
}